// round 7
// baseline (speedup 1.0000x reference)
#include <cuda_runtime.h>

#define BB 8
#define CI 128
#define MC 64
#define HH 64
#define WW 64
#define NH 128
#define NW 128
#define OP 112   // encoder outputs padded 100 -> 112

// Scratch (allocation-free per harness rules)
__device__ float g_m[BB * MC * HH * WW];                 // compressed features
__device__ float g_ker[BB * 25 * NH * NW];               // softmax kernels
__device__ __align__(16) float g_ew2t[MC * 9 * OP];      // weights [c][tap][o]
__device__ __align__(16) float g_cw2[CI * MC];           // compress weights [c][m]

typedef unsigned long long u64;

__device__ __forceinline__ u64 pk2(float lo, float hi) {
    u64 r; asm("mov.b64 %0, {%1,%2};" : "=l"(r) : "f"(lo), "f"(hi)); return r;
}
__device__ __forceinline__ float2 upk2(u64 v) {
    float2 f; asm("mov.b64 {%0,%1}, %2;" : "=f"(f.x), "=f"(f.y) : "l"(v)); return f;
}
__device__ __forceinline__ void fma2(u64 &acc, u64 a, u64 b) {
    asm("fma.rn.f32x2 %0, %1, %2, %0;" : "+l"(acc) : "l"(a), "l"(b));
}
__device__ __forceinline__ u64 ld2(const float* p) {
    return *reinterpret_cast<const u64*>(p);
}

// ---------------------------------------------------------------------------
// Prep: weight transposes. g_ew2t[c][tap][o] (o zero-padded to 112), g_cw2[c][m].
// ---------------------------------------------------------------------------
__global__ __launch_bounds__(256)
void k_prep(const float* __restrict__ ew, const float* __restrict__ cw) {
    int idx = blockIdx.x * 256 + threadIdx.x;
    const int n1 = MC * 9 * OP;
    if (idx < n1) {
        int c = idx / (9 * OP);
        int rem = idx - c * 9 * OP;
        int tap = rem / OP, o = rem - tap * OP;
        g_ew2t[idx] = (o < 100) ? ew[o * 576 + c * 9 + tap] : 0.f;
    } else if (idx < n1 + CI * MC) {
        int j = idx - n1;
        int c = j >> 6, m = j & 63;
        g_cw2[j] = cw[m * CI + c];
    }
}

// ---------------------------------------------------------------------------
// Kernel 1: 1x1 compress conv. block=(h-pair, b), 128 thr, 2 blocks/SM.
// ---------------------------------------------------------------------------
extern __shared__ float sm1[];
__global__ __launch_bounds__(128)
void k_compress(const float* __restrict__ x, const float* __restrict__ cb) {
    float* xs = sm1;                 // CI*2*68
    float* ws = sm1 + CI * 2 * 68;   // CI*64
    const int hb = blockIdx.x, b = blockIdx.y, tid = threadIdx.x;

    const float4* x4 = reinterpret_cast<const float4*>(x) + (size_t)b * (CI * HH * WW / 4);
    for (int idx = tid; idx < CI * 2 * 16; idx += 128) {
        int q = idx & 15, r = (idx >> 4) & 1, c = idx >> 5;
        float4 v = x4[(c * HH + 2 * hb + r) * 16 + q];
        *reinterpret_cast<float4*>(xs + (c * 2 + r) * 68 + q * 4) = v;
    }
    for (int idx = tid; idx < CI * MC / 4; idx += 128)
        reinterpret_cast<float4*>(ws)[idx] = reinterpret_cast<const float4*>(g_cw2)[idx];
    __syncthreads();

    const int mt = tid >> 4, wt = tid & 15;
    const int r = wt >> 3, w0 = (wt & 7) * 8, m0 = mt * 8;

    u64 acc[4][8];
    #pragma unroll
    for (int m = 0; m < 8; m++)
        #pragma unroll
        for (int wp = 0; wp < 4; wp++) acc[wp][m] = 0;

    #pragma unroll 2
    for (int c = 0; c < CI; c++) {
        const float* xr = xs + (c * 2 + r) * 68 + w0;
        u64 X0 = ld2(xr), X1 = ld2(xr + 2), X2 = ld2(xr + 4), X3 = ld2(xr + 6);
        const float* wr = ws + c * 64 + m0;
        #pragma unroll
        for (int m = 0; m < 8; m++) {
            float wv = wr[m];
            u64 W = pk2(wv, wv);
            fma2(acc[0][m], X0, W); fma2(acc[1][m], X1, W);
            fma2(acc[2][m], X2, W); fma2(acc[3][m], X3, W);
        }
    }
    #pragma unroll
    for (int m = 0; m < 8; m++) {
        float bv = cb[m0 + m];
        #pragma unroll
        for (int wp = 0; wp < 4; wp++) {
            float2 v = upk2(acc[wp][m]);
            *reinterpret_cast<float2*>(
                g_m + (((size_t)b * MC + m0 + m) * HH + 2 * hb + r) * WW + w0 + 2 * wp)
                = make_float2(v.x + bv, v.y + bv);
        }
    }
}

// ---------------------------------------------------------------------------
// Kernel 2: 3x3 encoder conv + bias + pixel-shuffle + softmax. block=(h,b),
// 224 thr = 28 o-tiles(4) x 8 w-tiles(8). acc[2][8] = 32 regs -> no spills
// at the (224,3) reg cap of 97. 39 KB smem -> 3 blocks/SM.
// Per (c,r): x-window 52B LDS + per tap 2 W-ld2; 48 fma2 -> ~67 B/warp-fma2.
// ---------------------------------------------------------------------------
extern __shared__ float sm2[];
__global__ __launch_bounds__(224, 3)
void k_encoder(const float* __restrict__ eb) {
    float* m_s = sm2;                 // 8*3*72 = 1728
    float* w_s = sm2 + 1728;          // 8*9*112 = 8064
    float* kt  = sm2;                 // alias, 112*64 = 7168
    const int h = blockIdx.x, b = blockIdx.y, tid = threadIdx.x;
    const int ot = tid >> 3, wt = tid & 7;
    const int o0 = ot * 4, w0 = wt * 8;

    u64 acc[2][8];   // [o-pair][w]
    #pragma unroll
    for (int j = 0; j < 2; j++) {
        int o = o0 + 2 * j;
        float b0 = (o < 100) ? __ldg(eb + o) : 0.f;
        float b1 = (o + 1 < 100) ? __ldg(eb + o + 1) : 0.f;
        u64 bb = pk2(b0, b1);
        #pragma unroll
        for (int k = 0; k < 8; k++) acc[j][k] = bb;
    }

    for (int cc0 = 0; cc0 < MC; cc0 += 8) {
        __syncthreads();
        for (int idx = tid; idx < 24 * 16; idx += 224) {
            int q = idx & 15, row = idx >> 4;       // row = c*3 + r
            int c = row / 3, r = row - c * 3;
            int hh = h + r - 1;
            float4 v = make_float4(0.f, 0.f, 0.f, 0.f);
            if ((unsigned)hh < HH)
                v = *reinterpret_cast<const float4*>(
                    g_m + (((size_t)b * MC + cc0 + c) * HH + hh) * WW + q * 4);
            *reinterpret_cast<float4*>(m_s + row * 72 + 4 + q * 4) = v;
        }
        for (int idx = tid; idx < 48; idx += 224) {
            int row = idx >> 1, e = idx & 1;
            *reinterpret_cast<float4*>(m_s + row * 72 + (e ? 68 : 0)) =
                make_float4(0.f, 0.f, 0.f, 0.f);
        }
        {
            const float4* wsrc = reinterpret_cast<const float4*>(g_ew2t + cc0 * 9 * OP);
            for (int idx = tid; idx < 8 * 9 * OP / 4; idx += 224)
                reinterpret_cast<float4*>(w_s)[idx] = wsrc[idx];
        }
        __syncthreads();

        #pragma unroll 1
        for (int c = 0; c < 8; c++) {
            #pragma unroll
            for (int r = 0; r < 3; r++) {
                const float* mr = m_s + (c * 3 + r) * 72 + w0;
                float xv[11];
                xv[0] = mr[3];
                float4 A = *reinterpret_cast<const float4*>(mr + 4);
                float4 Bv = *reinterpret_cast<const float4*>(mr + 8);
                float4 Cv = *reinterpret_cast<const float4*>(mr + 12);
                xv[1] = A.x; xv[2] = A.y; xv[3] = A.z; xv[4] = A.w;
                xv[5] = Bv.x; xv[6] = Bv.y; xv[7] = Bv.z; xv[8] = Bv.w;
                xv[9] = Cv.x; xv[10] = Cv.y;
                #pragma unroll
                for (int s = 0; s < 3; s++) {
                    const float* wr = w_s + (c * 9 + r * 3 + s) * OP + o0;
                    u64 W0 = ld2(wr), W1 = ld2(wr + 2);
                    #pragma unroll
                    for (int k = 0; k < 8; k++) {
                        u64 X = pk2(xv[k + s], xv[k + s]);
                        fma2(acc[0][k], X, W0);
                        fma2(acc[1][k], X, W1);
                    }
                }
            }
        }
    }
    __syncthreads();
    #pragma unroll
    for (int j = 0; j < 2; j++)
        #pragma unroll
        for (int k = 0; k < 8; k++) {
            float2 v = upk2(acc[j][k]);
            kt[(o0 + 2 * j) * 64 + w0 + k] = v.x;
            kt[(o0 + 2 * j + 1) * 64 + w0 + k] = v.y;
        }
    __syncthreads();

    for (int task = tid; task < 256; task += 224) {
        int sub = task >> 6, w2 = task & 63;
        int sh = sub >> 1, sw = sub & 1;
        float v[25]; float mx = -1e30f;
        #pragma unroll
        for (int t = 0; t < 25; t++) { v[t] = kt[(t * 4 + sub) * 64 + w2]; mx = fmaxf(mx, v[t]); }
        float ssum = 0.f;
        #pragma unroll
        for (int t = 0; t < 25; t++) { v[t] = __expf(v[t] - mx); ssum += v[t]; }
        float inv = 1.f / ssum;
        int oh = 2 * h + sh, ow = 2 * w2 + sw;
        #pragma unroll
        for (int t = 0; t < 25; t++)
            g_ker[(((size_t)b * 25 + t) * NH + oh) * NW + ow] = v[t] * inv;
    }
}

// ---------------------------------------------------------------------------
// Kernel 3: content-aware reassembly. block=(h, cg, b): 32 channels per
// block, 256 thr, 71.7 KB smem -> 3 blocks/SM (24 warps).
// ---------------------------------------------------------------------------
extern __shared__ float sm3[];
__global__ __launch_bounds__(256, 3)
void k_carafe(const float* __restrict__ x, float* __restrict__ out) {
    float* ker_s = sm3;           // 50*128 = 6400
    float* x_s   = sm3 + 6400;    // 160*72 = 11520
    const int h = blockIdx.x, cg = blockIdx.y, b = blockIdx.z, tid = threadIdx.x;
    const int cbase = cg * 32;

    for (int idx = tid; idx < 6400; idx += 256) {
        int ow = idx & 127, tp = idx >> 7;
        ker_s[idx] = g_ker[(((size_t)b * 25 + (tp >> 1)) * NH + 2 * h + (tp & 1)) * NW + ow];
    }
    for (int idx = tid; idx < 32 * 5 * 16; idx += 256) {
        int q = idx & 15, row = idx >> 4;           // row = c*5 + i
        int c = row / 5, i = row - c * 5;
        int hh = h + i - 2;
        float4 v = make_float4(0.f, 0.f, 0.f, 0.f);
        if ((unsigned)hh < HH)
            v = *reinterpret_cast<const float4*>(
                x + (((size_t)b * CI + cbase + c) * HH + hh) * WW + q * 4);
        *reinterpret_cast<float4*>(x_s + row * 72 + 4 + q * 4) = v;
    }
    for (int idx = tid; idx < 320; idx += 256) {
        int row = idx >> 1, e = idx & 1;
        *reinterpret_cast<float4*>(x_s + row * 72 + (e ? 68 : 0)) =
            make_float4(0.f, 0.f, 0.f, 0.f);
    }
    __syncthreads();

    const int w = tid & 63, co = tid >> 6;   // co 0..3 -> 8 channels
    const float* kb = ker_s + 2 * w;
    const float* xb = x_s + (size_t)(co * 8) * 360 + w + 2;

    u64 acc[2][8];
    #pragma unroll
    for (int p = 0; p < 2; p++)
        #pragma unroll
        for (int cc = 0; cc < 8; cc++) acc[p][cc] = 0;

    #pragma unroll
    for (int i = 0; i < 5; i++) {
        #pragma unroll
        for (int j = 0; j < 5; j++) {
            const int t = i * 5 + j;
            u64 K0 = ld2(kb + (2 * t) * 128);
            u64 K1 = ld2(kb + (2 * t + 1) * 128);
            #pragma unroll
            for (int cc = 0; cc < 8; cc++) {
                float xv = xb[cc * 360 + i * 72 + j];
                u64 X = pk2(xv, xv);
                fma2(acc[0][cc], X, K0);
                fma2(acc[1][cc], X, K1);
            }
        }
    }
    #pragma unroll
    for (int p = 0; p < 2; p++)
        #pragma unroll
        for (int cc = 0; cc < 8; cc++) {
            float2 v = upk2(acc[p][cc]);
            int ch = cbase + co * 8 + cc;
            *reinterpret_cast<float2*>(
                out + (((size_t)b * CI + ch) * NH + 2 * h + p) * NW + 2 * w) = v;
        }
}

// ---------------------------------------------------------------------------
extern "C" void kernel_launch(void* const* d_in, const int* in_sizes, int n_in,
                              void* d_out, int out_size) {
    const float* x  = (const float*)d_in[0];
    const float* cw = (const float*)d_in[1];
    const float* cb = (const float*)d_in[2];
    const float* ew = (const float*)d_in[3];
    const float* eb = (const float*)d_in[4];
    float* out = (float*)d_out;

    const int smem1 = (CI * 2 * 68 + CI * MC) * 4;     // 102400
    const int smem2 = (1728 + 8064) * 4;               // 39168
    const int smem3 = (6400 + 160 * 72) * 4;           // 71680
    cudaFuncSetAttribute(k_compress, cudaFuncAttributeMaxDynamicSharedMemorySize, smem1);
    cudaFuncSetAttribute(k_encoder,  cudaFuncAttributeMaxDynamicSharedMemorySize, smem2);
    cudaFuncSetAttribute(k_carafe,   cudaFuncAttributeMaxDynamicSharedMemorySize, smem3);

    k_prep<<<(MC * 9 * OP + CI * MC + 255) / 256, 256>>>(ew, cw);
    k_compress<<<dim3(HH / 2, BB), 128, smem1>>>(x, cb);
    k_encoder<<<dim3(HH, BB), 224, smem2>>>(eb);
    k_carafe<<<dim3(HH, 4, BB), 256, smem3>>>(x, out);
}

// round 8
// speedup vs baseline: 1.5963x; 1.5963x over previous
#include <cuda_runtime.h>

#define BB 8
#define CI 128
#define MC 64
#define HH 64
#define WW 64
#define NH 128
#define NW 128
#define OP 112   // encoder outputs padded 100 -> 112 (14 o-tiles of 8)

// Scratch (allocation-free per harness rules)
__device__ float g_m[BB * MC * HH * WW];                 // compressed features
__device__ float g_ker[BB * 25 * NH * NW];               // softmax kernels
__device__ __align__(16) float g_ew2t[MC * 9 * OP];      // weights [c][tap][o]
__device__ __align__(16) float g_cw2[CI * MC];           // compress weights [c][m]

typedef unsigned long long u64;

__device__ __forceinline__ u64 pk2(float lo, float hi) {
    u64 r; asm("mov.b64 %0, {%1,%2};" : "=l"(r) : "f"(lo), "f"(hi)); return r;
}
__device__ __forceinline__ float2 upk2(u64 v) {
    float2 f; asm("mov.b64 {%0,%1}, %2;" : "=f"(f.x), "=f"(f.y) : "l"(v)); return f;
}
__device__ __forceinline__ void fma2(u64 &acc, u64 a, u64 b) {
    asm("fma.rn.f32x2 %0, %1, %2, %0;" : "+l"(acc) : "l"(a), "l"(b));
}
__device__ __forceinline__ u64 ld2(const float* p) {
    return *reinterpret_cast<const u64*>(p);
}

// ---------------------------------------------------------------------------
// Prep: weight transposes. g_ew2t[c][tap][o] (o zero-padded to 112), g_cw2[c][m].
// ---------------------------------------------------------------------------
__global__ __launch_bounds__(256)
void k_prep(const float* __restrict__ ew, const float* __restrict__ cw) {
    int idx = blockIdx.x * 256 + threadIdx.x;
    const int n1 = MC * 9 * OP;
    if (idx < n1) {
        int c = idx / (9 * OP);
        int rem = idx - c * 9 * OP;
        int tap = rem / OP, o = rem - tap * OP;
        g_ew2t[idx] = (o < 100) ? ew[o * 576 + c * 9 + tap] : 0.f;
    } else if (idx < n1 + CI * MC) {
        int j = idx - n1;
        int c = j >> 6, m = j & 63;
        g_cw2[j] = cw[m * CI + c];
    }
}

// ---------------------------------------------------------------------------
// Kernel 1: 1x1 compress conv. block=(h-pair, b), 128 thr, 2 blocks/SM.
// (R4 version, best measured)
// ---------------------------------------------------------------------------
extern __shared__ float sm1[];
__global__ __launch_bounds__(128)
void k_compress(const float* __restrict__ x, const float* __restrict__ cb) {
    float* xs = sm1;                 // CI*2*68
    float* ws = sm1 + CI * 2 * 68;   // CI*64
    const int hb = blockIdx.x, b = blockIdx.y, tid = threadIdx.x;

    const float4* x4 = reinterpret_cast<const float4*>(x) + (size_t)b * (CI * HH * WW / 4);
    for (int idx = tid; idx < CI * 2 * 16; idx += 128) {
        int q = idx & 15, r = (idx >> 4) & 1, c = idx >> 5;
        float4 v = x4[(c * HH + 2 * hb + r) * 16 + q];
        *reinterpret_cast<float4*>(xs + (c * 2 + r) * 68 + q * 4) = v;
    }
    for (int idx = tid; idx < CI * MC / 4; idx += 128)
        reinterpret_cast<float4*>(ws)[idx] = reinterpret_cast<const float4*>(g_cw2)[idx];
    __syncthreads();

    const int mt = tid >> 4, wt = tid & 15;
    const int r = wt >> 3, w0 = (wt & 7) * 8, m0 = mt * 8;

    u64 acc[4][8];
    #pragma unroll
    for (int m = 0; m < 8; m++)
        #pragma unroll
        for (int wp = 0; wp < 4; wp++) acc[wp][m] = 0;

    #pragma unroll 2
    for (int c = 0; c < CI; c++) {
        const float* xr = xs + (c * 2 + r) * 68 + w0;
        u64 X0 = ld2(xr), X1 = ld2(xr + 2), X2 = ld2(xr + 4), X3 = ld2(xr + 6);
        const float* wr = ws + c * 64 + m0;
        #pragma unroll
        for (int m = 0; m < 8; m++) {
            float wv = wr[m];
            u64 W = pk2(wv, wv);
            fma2(acc[0][m], X0, W); fma2(acc[1][m], X1, W);
            fma2(acc[2][m], X2, W); fma2(acc[3][m], X3, W);
        }
    }
    #pragma unroll
    for (int m = 0; m < 8; m++) {
        float bv = cb[m0 + m];
        #pragma unroll
        for (int wp = 0; wp < 4; wp++) {
            float2 v = upk2(acc[wp][m]);
            *reinterpret_cast<float2*>(
                g_m + (((size_t)b * MC + m0 + m) * HH + 2 * hb + r) * WW + w0 + 2 * wp)
                = make_float2(v.x + bv, v.y + bv);
        }
    }
}

// ---------------------------------------------------------------------------
// Kernel 2: 3x3 encoder conv + bias + pixel-shuffle + softmax. (R4 version,
// best measured.) block=(h,b), 224 thr = 14 o-tiles(8) x 16 w-tiles(4).
// ---------------------------------------------------------------------------
extern __shared__ float sm2[];
__global__ __launch_bounds__(224)
void k_encoder(const float* __restrict__ eb) {
    float* m_s = sm2;                 // 8*3*72 = 1728
    float* w_s = sm2 + 1728;          // 8*9*112 = 8064
    float* kt  = sm2;                 // alias, 112*64 = 7168
    const int h = blockIdx.x, b = blockIdx.y, tid = threadIdx.x;
    const int ot = tid >> 4, wt = tid & 15;
    const int o0 = ot * 8, w0 = wt * 4;

    u64 acc[4][4];   // [o-pair][w]
    #pragma unroll
    for (int j = 0; j < 4; j++) {
        int o = o0 + 2 * j;
        float b0 = (o < 100) ? __ldg(eb + o) : 0.f;
        float b1 = (o + 1 < 100) ? __ldg(eb + o + 1) : 0.f;
        u64 bb = pk2(b0, b1);
        #pragma unroll
        for (int k = 0; k < 4; k++) acc[j][k] = bb;
    }

    for (int cc0 = 0; cc0 < MC; cc0 += 8) {
        __syncthreads();
        for (int idx = tid; idx < 24 * 16; idx += 224) {
            int q = idx & 15, row = idx >> 4;       // row = c*3 + r
            int c = row / 3, r = row - c * 3;
            int hh = h + r - 1;
            float4 v = make_float4(0.f, 0.f, 0.f, 0.f);
            if ((unsigned)hh < HH)
                v = *reinterpret_cast<const float4*>(
                    g_m + (((size_t)b * MC + cc0 + c) * HH + hh) * WW + q * 4);
            *reinterpret_cast<float4*>(m_s + row * 72 + 4 + q * 4) = v;
        }
        for (int idx = tid; idx < 48; idx += 224) {
            int row = idx >> 1, e = idx & 1;
            *reinterpret_cast<float4*>(m_s + row * 72 + (e ? 68 : 0)) =
                make_float4(0.f, 0.f, 0.f, 0.f);
        }
        {
            const float4* wsrc = reinterpret_cast<const float4*>(g_ew2t + cc0 * 9 * OP);
            for (int idx = tid; idx < 8 * 9 * OP / 4; idx += 224)
                reinterpret_cast<float4*>(w_s)[idx] = wsrc[idx];
        }
        __syncthreads();

        #pragma unroll 1
        for (int c = 0; c < 8; c++) {
            #pragma unroll
            for (int r = 0; r < 3; r++) {
                const float* mr = m_s + (c * 3 + r) * 72 + w0;
                float4 A = *reinterpret_cast<const float4*>(mr);
                float4 Bv = *reinterpret_cast<const float4*>(mr + 4);
                float4 Cv = *reinterpret_cast<const float4*>(mr + 8);
                float xv[7];
                xv[0] = A.w;
                xv[1] = Bv.x; xv[2] = Bv.y; xv[3] = Bv.z; xv[4] = Bv.w;
                xv[5] = Cv.x; xv[6] = Cv.y;
                #pragma unroll
                for (int s = 0; s < 3; s++) {
                    const float* wr = w_s + (c * 9 + r * 3 + s) * OP + o0;
                    u64 W0 = ld2(wr), W1 = ld2(wr + 2), W2 = ld2(wr + 4), W3 = ld2(wr + 6);
                    #pragma unroll
                    for (int k = 0; k < 4; k++) {
                        u64 X = pk2(xv[k + s], xv[k + s]);
                        fma2(acc[0][k], X, W0);
                        fma2(acc[1][k], X, W1);
                        fma2(acc[2][k], X, W2);
                        fma2(acc[3][k], X, W3);
                    }
                }
            }
        }
    }
    __syncthreads();
    #pragma unroll
    for (int j = 0; j < 4; j++)
        #pragma unroll
        for (int k = 0; k < 4; k++) {
            float2 v = upk2(acc[j][k]);
            kt[(o0 + 2 * j) * 64 + w0 + k] = v.x;
            kt[(o0 + 2 * j + 1) * 64 + w0 + k] = v.y;
        }
    __syncthreads();

    for (int task = tid; task < 256; task += 224) {
        int sub = task >> 6, w2 = task & 63;
        int sh = sub >> 1, sw = sub & 1;
        float v[25]; float mx = -1e30f;
        #pragma unroll
        for (int t = 0; t < 25; t++) { v[t] = kt[(t * 4 + sub) * 64 + w2]; mx = fmaxf(mx, v[t]); }
        float ssum = 0.f;
        #pragma unroll
        for (int t = 0; t < 25; t++) { v[t] = __expf(v[t] - mx); ssum += v[t]; }
        float inv = 1.f / ssum;
        int oh = 2 * h + sh, ow = 2 * w2 + sw;
        #pragma unroll
        for (int t = 0; t < 25; t++)
            g_ker[(((size_t)b * 25 + t) * NH + oh) * NW + ow] = v[t] * inv;
    }
}

// ---------------------------------------------------------------------------
// Kernel 3: content-aware reassembly. block=(h, cg, b): 16 channels per
// block, 256 thr, 47.5 KB smem -> 4 blocks/SM (32 warps), <=64 regs.
// Thread = (w, co 0..3) -> 4 channels, 2 oh x 2 ow each.
// ---------------------------------------------------------------------------
extern __shared__ float sm3[];
__global__ __launch_bounds__(256, 4)
void k_carafe(const float* __restrict__ x, float* __restrict__ out) {
    float* ker_s = sm3;           // 50*128 = 6400
    float* x_s   = sm3 + 6400;    // 80*72 = 5760
    const int h = blockIdx.x, cg = blockIdx.y, b = blockIdx.z, tid = threadIdx.x;
    const int cbase = cg * 16;

    // stage ker rows (both oh of the pair) as float4
    for (int idx = tid; idx < 50 * 32; idx += 256) {
        int q = idx & 31, tp = idx >> 5;
        *reinterpret_cast<float4*>(ker_s + tp * 128 + q * 4) =
            *reinterpret_cast<const float4*>(
                g_ker + (((size_t)b * 25 + (tp >> 1)) * NH + 2 * h + (tp & 1)) * NW + q * 4);
    }
    // stage x: 16 channels x 5 rows, padded cols
    for (int idx = tid; idx < 16 * 5 * 16; idx += 256) {
        int q = idx & 15, row = idx >> 4;           // row = c*5 + i
        int c = row / 5, i = row - c * 5;
        int hh = h + i - 2;
        float4 v = make_float4(0.f, 0.f, 0.f, 0.f);
        if ((unsigned)hh < HH)
            v = *reinterpret_cast<const float4*>(
                x + (((size_t)b * CI + cbase + c) * HH + hh) * WW + q * 4);
        *reinterpret_cast<float4*>(x_s + row * 72 + 4 + q * 4) = v;
    }
    for (int idx = tid; idx < 160; idx += 256) {
        int row = idx >> 1, e = idx & 1;
        *reinterpret_cast<float4*>(x_s + row * 72 + (e ? 68 : 0)) =
            make_float4(0.f, 0.f, 0.f, 0.f);
    }
    __syncthreads();

    const int w = tid & 63, co = tid >> 6;   // co 0..3 -> 4 channels
    const float* kb = ker_s + 2 * w;
    const float* xb = x_s + (size_t)(co * 4) * 360 + w + 2;

    u64 acc[2][4];
    #pragma unroll
    for (int p = 0; p < 2; p++)
        #pragma unroll
        for (int cc = 0; cc < 4; cc++) acc[p][cc] = 0;

    #pragma unroll
    for (int i = 0; i < 5; i++) {
        #pragma unroll
        for (int j = 0; j < 5; j++) {
            const int t = i * 5 + j;
            u64 K0 = ld2(kb + (2 * t) * 128);
            u64 K1 = ld2(kb + (2 * t + 1) * 128);
            #pragma unroll
            for (int cc = 0; cc < 4; cc++) {
                float xv = xb[cc * 360 + i * 72 + j];
                u64 X = pk2(xv, xv);
                fma2(acc[0][cc], X, K0);
                fma2(acc[1][cc], X, K1);
            }
        }
    }
    #pragma unroll
    for (int p = 0; p < 2; p++)
        #pragma unroll
        for (int cc = 0; cc < 4; cc++) {
            float2 v = upk2(acc[p][cc]);
            int ch = cbase + co * 4 + cc;
            *reinterpret_cast<float2*>(
                out + (((size_t)b * CI + ch) * NH + 2 * h + p) * NW + 2 * w) = v;
        }
}

// ---------------------------------------------------------------------------
extern "C" void kernel_launch(void* const* d_in, const int* in_sizes, int n_in,
                              void* d_out, int out_size) {
    const float* x  = (const float*)d_in[0];
    const float* cw = (const float*)d_in[1];
    const float* cb = (const float*)d_in[2];
    const float* ew = (const float*)d_in[3];
    const float* eb = (const float*)d_in[4];
    float* out = (float*)d_out;

    const int smem1 = (CI * 2 * 68 + CI * MC) * 4;     // 102400
    const int smem2 = (1728 + 8064) * 4;               // 39168
    const int smem3 = (6400 + 80 * 72) * 4;            // 48640
    cudaFuncSetAttribute(k_compress, cudaFuncAttributeMaxDynamicSharedMemorySize, smem1);
    cudaFuncSetAttribute(k_encoder,  cudaFuncAttributeMaxDynamicSharedMemorySize, smem2);
    cudaFuncSetAttribute(k_carafe,   cudaFuncAttributeMaxDynamicSharedMemorySize, smem3);

    k_prep<<<(MC * 9 * OP + CI * MC + 255) / 256, 256>>>(ew, cw);
    k_compress<<<dim3(HH / 2, BB), 128, smem1>>>(x, cb);
    k_encoder<<<dim3(HH, BB), 224, smem2>>>(eb);
    k_carafe<<<dim3(HH, 8, BB), 256, smem3>>>(x, out);
}